// round 1
// baseline (speedup 1.0000x reference)
#include <cuda_runtime.h>

// Problem constants
#define NB 32768
#define NL 1024
#define NK 5
#define FEA 1028           // NL + 4
#define MD 50              // MEM_DIM
#define DD 32              // DATE_DIM
#define SHRINKF 0.0025f
#define EPSF 1e-12f

// Scratch (allocation-free rule: __device__ globals)
__device__ float g_M2[MD * NL];        // conv-folded mem_W: 200 KB
__device__ float g_att[NB * MD];       // 6.5 MB

// ---------------------------------------------------------------------------
// f32x2 helpers (FFMA2 path — only reachable via PTX)
// ---------------------------------------------------------------------------
__device__ __forceinline__ void fma2(unsigned long long& d,
                                     unsigned long long a,
                                     unsigned long long b) {
    asm("fma.rn.f32x2 %0, %1, %2, %0;" : "+l"(d) : "l"(a), "l"(b));
}
__device__ __forceinline__ unsigned long long pk_dup(float v) {
    unsigned long long r;
    asm("mov.b64 %0, {%1, %1};" : "=l"(r) : "f"(v));
    return r;
}
__device__ __forceinline__ float2 unpk(unsigned long long v) {
    float2 r;
    asm("mov.b64 {%0, %1}, %2;" : "=f"(r.x), "=f"(r.y) : "l"(v));
    return r;
}

// ---------------------------------------------------------------------------
// Kernel 1: fold transposed-conv (flipped convt_w, VALID) into mem_W.
// M2[d][i] = sum_k mem_W[d][i+k] * convt_w[4-k],  i in [0,1024)
// ---------------------------------------------------------------------------
__global__ void k_prep_m2(const float* __restrict__ mem_W,
                          const float* __restrict__ convt_w) {
    int idx = blockIdx.x * blockDim.x + threadIdx.x;
    if (idx >= MD * NL) return;
    int d = idx / NL, i = idx - d * NL;
    float s = 0.f;
#pragma unroll
    for (int k = 0; k < NK; k++)
        s += mem_W[d * FEA + i + k] * convt_w[NK - 1 - k];
    g_M2[idx] = s;
}

// ---------------------------------------------------------------------------
// Kernel 2: att = normalize(shrink(softmax(date_vector @ date_W.T)))
// One warp per row. Lane l owns columns j=l and j=l+32.
// ---------------------------------------------------------------------------
__global__ __launch_bounds__(256) void k_att(const float* __restrict__ date_vec,
                                             const float* __restrict__ date_W) {
    __shared__ float dWt[DD][64];     // transposed, zero-padded to 64 cols
    __shared__ float dv[8][DD];
    int tid = threadIdx.x;
    for (int idx = tid; idx < DD * 64; idx += 256) dWt[idx / 64][idx % 64] = 0.f;
    __syncthreads();
    for (int idx = tid; idx < MD * DD; idx += 256) {
        int j = idx / DD, f = idx - j * DD;
        dWt[f][j] = date_W[idx];
    }
    __syncthreads();

    int w = tid >> 5, l = tid & 31;
    int b = blockIdx.x * 8 + w;
    dv[w][l] = date_vec[b * DD + l];
    __syncwarp();

    int j2 = l + 32;
    float s1 = 0.f, s2 = 0.f;
#pragma unroll
    for (int f = 0; f < DD; f++) {
        float d = dv[w][f];
        s1 += d * dWt[f][l];
        s2 += d * dWt[f][j2];
    }
    bool v2ok = (j2 < MD);

    // softmax over 50
    float m = fmaxf(s1, v2ok ? s2 : -1e30f);
#pragma unroll
    for (int o = 16; o; o >>= 1) m = fmaxf(m, __shfl_xor_sync(~0u, m, o));
    float e1 = expf(s1 - m);
    float e2 = v2ok ? expf(s2 - m) : 0.f;
    float sum = e1 + e2;
#pragma unroll
    for (int o = 16; o; o >>= 1) sum += __shfl_xor_sync(~0u, sum, o);
    float a1 = e1 / sum, a2 = e2 / sum;

    // shrink transform + L1 renorm
    float t1 = a1 - SHRINKF;
    float v1 = fmaxf(t1, 0.f) * a1 / (fabsf(t1) + EPSF);
    float t2 = a2 - SHRINKF;
    float v2 = fmaxf(t2, 0.f) * a2 / (fabsf(t2) + EPSF);
    float sa = fabsf(v1) + fabsf(v2);
#pragma unroll
    for (int o = 16; o; o >>= 1) sa += __shfl_xor_sync(~0u, sa, o);
    float inv = 1.f / (sa + EPSF);

    g_att[b * MD + l] = v1 * inv;
    if (v2ok) g_att[b * MD + j2] = v2 * inv;
}

// ---------------------------------------------------------------------------
// Kernel 3: weight/bias per row (streaming read of x, 128 MB).
// One warp per row; writes directly into d_out tail.
// ---------------------------------------------------------------------------
__global__ __launch_bounds__(256) void k_wb(const float* __restrict__ x,
                                            const float* __restrict__ fcw_w,
                                            const float* __restrict__ fcw_b,
                                            const float* __restrict__ fcb_w,
                                            const float* __restrict__ fcb_b,
                                            float* __restrict__ out) {
    __shared__ float4 wS[256], bS[256];
    int tid = threadIdx.x;
    wS[tid] = ((const float4*)fcw_w)[tid];
    bS[tid] = ((const float4*)fcb_w)[tid];
    __syncthreads();

    int w = tid >> 5, l = tid & 31;
    int b = blockIdx.x * 8 + w;
    const float4* xr = (const float4*)(x + (size_t)b * NL);
    float wa = 0.f, ba = 0.f;
#pragma unroll
    for (int i = 0; i < 8; i++) {
        float4 xv = xr[i * 32 + l];
        float4 fw = wS[i * 32 + l];
        float4 fb = bS[i * 32 + l];
        wa += xv.x * fw.x + xv.y * fw.y + xv.z * fw.z + xv.w * fw.w;
        ba += xv.x * fb.x + xv.y * fb.y + xv.z * fb.z + xv.w * fb.w;
    }
#pragma unroll
    for (int o = 16; o; o >>= 1) {
        wa += __shfl_xor_sync(~0u, wa, o);
        ba += __shfl_xor_sync(~0u, ba, o);
    }
    if (l == 0) {
        out[(size_t)NB * NL + b] = tanhf(wa + fcw_b[0]) * 0.5f + 1.0f;
        out[(size_t)NB * NL + NB + b] = tanhf(ba + fcb_b[0]) * 0.5f;
    }
}

// ---------------------------------------------------------------------------
// Kernel 4: out[b][i] = (att[b,:] @ M2[:,i]) * weight[b] + bias[b]
// Block tile 64 rows x 128 cols; thread micro-tile 8 rows (4 f32x2 pairs) x 4 cols.
// ---------------------------------------------------------------------------
#define BM 64
#define BN 128
__global__ __launch_bounds__(256) void k_gemm(float* __restrict__ out) {
    __shared__ float attS[MD][BM];      // [k][row], row-pairs contiguous
    __shared__ float m2S[MD][BN];       // [k][col]
    __shared__ float wS[BM], biS[BM];

    int tid = threadIdx.x;
    int brow = blockIdx.y * BM;
    int bcol = blockIdx.x * BN;

    // att tile (transposed fill; global reads strided but L2-resident)
    for (int idx = tid; idx < MD * BM; idx += 256) {
        int k = idx / BM, r = idx - k * BM;
        attS[k][r] = g_att[(size_t)(brow + r) * MD + k];
    }
    // M2 tile (coalesced)
    for (int idx = tid; idx < MD * BN; idx += 256) {
        int k = idx / BN, c = idx - k * BN;
        m2S[k][c] = g_M2[k * NL + bcol + c];
    }
    if (tid < BM) {
        wS[tid]  = out[(size_t)NB * NL + brow + tid];
        biS[tid] = out[(size_t)NB * NL + NB + brow + tid];
    }
    __syncthreads();

    int tx = tid & 31, ty = tid >> 5;
    int r0 = ty * 8;          // 8 rows -> 4 f32x2 pairs
    int c0 = tx * 4;          // 4 cols

    unsigned long long acc[4][4];
#pragma unroll
    for (int p = 0; p < 4; p++)
#pragma unroll
        for (int c = 0; c < 4; c++) acc[p][c] = 0ull;

#pragma unroll 10
    for (int k = 0; k < MD; k++) {
        // a: rows r0..r0+7 as packed pairs (broadcast across warp lanes)
        ulonglong2 a01 = *(const ulonglong2*)&attS[k][r0];      // pairs (r0,r0+1),(r0+2,r0+3)
        ulonglong2 a23 = *(const ulonglong2*)&attS[k][r0 + 4];  // pairs (r0+4..r0+7)
        float4 bf = *(const float4*)&m2S[k][c0];
        unsigned long long b0 = pk_dup(bf.x), b1 = pk_dup(bf.y),
                           b2 = pk_dup(bf.z), b3 = pk_dup(bf.w);
        fma2(acc[0][0], a01.x, b0); fma2(acc[0][1], a01.x, b1);
        fma2(acc[0][2], a01.x, b2); fma2(acc[0][3], a01.x, b3);
        fma2(acc[1][0], a01.y, b0); fma2(acc[1][1], a01.y, b1);
        fma2(acc[1][2], a01.y, b2); fma2(acc[1][3], a01.y, b3);
        fma2(acc[2][0], a23.x, b0); fma2(acc[2][1], a23.x, b1);
        fma2(acc[2][2], a23.x, b2); fma2(acc[2][3], a23.x, b3);
        fma2(acc[3][0], a23.y, b0); fma2(acc[3][1], a23.y, b1);
        fma2(acc[3][2], a23.y, b2); fma2(acc[3][3], a23.y, b3);
    }

    // epilogue: *weight + bias, STG.128 per row
#pragma unroll
    for (int p = 0; p < 4; p++) {
        int r = r0 + 2 * p;
        float w0 = wS[r], bv0 = biS[r];
        float w1 = wS[r + 1], bv1 = biS[r + 1];
        float2 u0 = unpk(acc[p][0]);
        float2 u1 = unpk(acc[p][1]);
        float2 u2 = unpk(acc[p][2]);
        float2 u3 = unpk(acc[p][3]);
        float4 v0, v1;
        v0.x = u0.x * w0 + bv0; v0.y = u1.x * w0 + bv0;
        v0.z = u2.x * w0 + bv0; v0.w = u3.x * w0 + bv0;
        v1.x = u0.y * w1 + bv1; v1.y = u1.y * w1 + bv1;
        v1.z = u2.y * w1 + bv1; v1.w = u3.y * w1 + bv1;
        *(float4*)&out[(size_t)(brow + r) * NL + bcol + c0] = v0;
        *(float4*)&out[(size_t)(brow + r + 1) * NL + bcol + c0] = v1;
    }
}

// ---------------------------------------------------------------------------
extern "C" void kernel_launch(void* const* d_in, const int* in_sizes, int n_in,
                              void* d_out, int out_size) {
    const float* x        = (const float*)d_in[0];
    const float* date_vec = (const float*)d_in[1];
    // d_in[2] (conv_w) is dead code in the reference
    const float* convt_w  = (const float*)d_in[3];
    const float* mem_W    = (const float*)d_in[4];
    const float* date_W   = (const float*)d_in[5];
    const float* fcw_w    = (const float*)d_in[6];
    const float* fcw_b    = (const float*)d_in[7];
    const float* fcb_w    = (const float*)d_in[8];
    const float* fcb_b    = (const float*)d_in[9];
    float* out = (float*)d_out;

    k_prep_m2<<<(MD * NL + 255) / 256, 256>>>(mem_W, convt_w);
    k_att<<<NB / 8, 256>>>(date_vec, date_W);
    k_wb<<<NB / 8, 256>>>(x, fcw_w, fcw_b, fcb_w, fcb_b, out);
    dim3 g(NL / BN, NB / BM);
    k_gemm<<<g, 256>>>(out);
}